// round 4
// baseline (speedup 1.0000x reference)
#include <cuda_runtime.h>
#include <math.h>

#define B_  64
#define T_  512
#define D_  1024
#define H_  1024
#define G4  4096   // 4*H

#define NCTA   128
#define NTHR   256
#define COLS_PER_CTA 32          // permuted gate columns per CTA (= 8 hidden cells)
#define KCHUNK 64
#define NCHUNK (H_ / KCHUNK)     // 16
#define HS_DUP 128               // duplicated batch width (2*B_)
#define HS_ELEMS (KCHUNK * HS_DUP)   // floats per ping-pong buffer (8192)

// ---------------- device-global scratch ----------------
__device__ float g_Wip[D_ * G4];              // permuted Wi
__device__ float g_Whp[H_ * G4];              // permuted Wh
__device__ float g_bp[G4];                    // permuted bias
__device__ float g_xp[(size_t)B_ * T_ * G4];  // x_proj [b*T+t][4H] permuted cols
__device__ float g_hT[2][H_ * B_];            // hidden state, TRANSPOSED [hc][b], double buffered
__device__ unsigned g_bar;                    // grid barrier counter

typedef unsigned long long ull;

// ---------------- packed f32x2 helpers ----------------
__device__ __forceinline__ ull pack2(float lo, float hi) {
    ull r; asm("mov.b64 %0, {%1, %2};" : "=l"(r) : "f"(lo), "f"(hi)); return r;
}
__device__ __forceinline__ void unpack2(ull v, float& lo, float& hi) {
    asm("mov.b64 {%0, %1}, %2;" : "=f"(lo), "=f"(hi) : "l"(v));
}
__device__ __forceinline__ void fma2(ull& d, ull a, ull b) {
    asm("fma.rn.f32x2 %0, %1, %2, %0;" : "+l"(d) : "l"(a), "l"(b));
}
__device__ __forceinline__ float sigmoidf_(float x) { return 1.0f / (1.0f + expf(-x)); }

// ---------------- phase 0: permute weights (gate-interleave columns) ----------
// new col n' = hc*4 + g  <-  old col g*1024 + hc
__global__ void permute_kernel(const float* __restrict__ Wi,
                               const float* __restrict__ Wh,
                               const float* __restrict__ b) {
    int idx = blockIdx.x * blockDim.x + threadIdx.x;   // 0 .. 4M-1
    int k  = idx >> 12;
    int np = idx & 4095;
    int hc = np >> 2;
    int gg = np & 3;
    int src = (k << 12) + (gg << 10) + hc;
    g_Wip[idx] = Wi[src];
    g_Whp[idx] = Wh[src];
    if (idx < G4) g_bp[idx] = b[((idx & 3) << 10) + (idx >> 2)];
    if (idx == 0) g_bar = 0u;
}

// ---------------- phase 1: x_proj = X @ Wip + bp (unchanged) ----------
__global__ __launch_bounds__(256)
void gemm_xproj(const float* __restrict__ X) {
    __shared__ float As[16][128];
    __shared__ float Bs[16][64];

    const int tid = threadIdx.x;
    const int m0 = blockIdx.y * 128;
    const int n0 = blockIdx.x * 64;
    const int tx = tid & 15;
    const int ty = tid >> 4;

    const int am = tid >> 1;
    const int ak = (tid & 1) * 4;
    const float* Aptr = X + (size_t)(m0 + am) * 1024 + ak;
    const int brow = tid >> 4;
    const int bcol = (tid & 15) * 4;
    const float* Bptr = g_Wip + (size_t)brow * G4 + n0 + bcol;

    float4 a0 = *(const float4*)(Aptr);
    float4 a1 = *(const float4*)(Aptr + 8);
    float4 bv = *(const float4*)(Bptr);

    ull acc[4][4];
    #pragma unroll
    for (int i = 0; i < 4; ++i)
        #pragma unroll
        for (int j = 0; j < 4; ++j) acc[i][j] = 0ULL;

    for (int kt = 0; kt < 64; ++kt) {
        As[ak + 0][am] = a0.x; As[ak + 1][am] = a0.y;
        As[ak + 2][am] = a0.z; As[ak + 3][am] = a0.w;
        As[ak + 8][am] = a1.x; As[ak + 9][am] = a1.y;
        As[ak +10][am] = a1.z; As[ak +11][am] = a1.w;
        *(float4*)&Bs[brow][bcol] = bv;
        __syncthreads();

        if (kt < 63) {
            Aptr += 16;
            Bptr += (size_t)16 * G4;
            a0 = *(const float4*)(Aptr);
            a1 = *(const float4*)(Aptr + 8);
            bv = *(const float4*)(Bptr);
        }

        #pragma unroll
        for (int k = 0; k < 16; ++k) {
            const ulonglong2* ap = (const ulonglong2*)&As[k][ty * 8];
            ulonglong2 A0 = ap[0];
            ulonglong2 A1 = ap[1];
            float4 b4 = *(const float4*)&Bs[k][tx * 4];
            ull bp0 = pack2(b4.x, b4.x);
            ull bp1 = pack2(b4.y, b4.y);
            ull bp2 = pack2(b4.z, b4.z);
            ull bp3 = pack2(b4.w, b4.w);
            fma2(acc[0][0], A0.x, bp0); fma2(acc[0][1], A0.x, bp1);
            fma2(acc[0][2], A0.x, bp2); fma2(acc[0][3], A0.x, bp3);
            fma2(acc[1][0], A0.y, bp0); fma2(acc[1][1], A0.y, bp1);
            fma2(acc[1][2], A0.y, bp2); fma2(acc[1][3], A0.y, bp3);
            fma2(acc[2][0], A1.x, bp0); fma2(acc[2][1], A1.x, bp1);
            fma2(acc[2][2], A1.x, bp2); fma2(acc[2][3], A1.x, bp3);
            fma2(acc[3][0], A1.y, bp0); fma2(acc[3][1], A1.y, bp1);
            fma2(acc[3][2], A1.y, bp2); fma2(acc[3][3], A1.y, bp3);
        }
        __syncthreads();
    }

    float4 bias = *(const float4*)(g_bp + n0 + tx * 4);
    #pragma unroll
    for (int mp = 0; mp < 4; ++mp) {
        float lo0, hi0, lo1, hi1, lo2, hi2, lo3, hi3;
        unpack2(acc[mp][0], lo0, hi0);
        unpack2(acc[mp][1], lo1, hi1);
        unpack2(acc[mp][2], lo2, hi2);
        unpack2(acc[mp][3], lo3, hi3);
        int m = m0 + ty * 8 + mp * 2;
        float4 r0 = make_float4(lo0 + bias.x, lo1 + bias.y, lo2 + bias.z, lo3 + bias.w);
        float4 r1 = make_float4(hi0 + bias.x, hi1 + bias.y, hi2 + bias.z, hi3 + bias.w);
        *(float4*)&g_xp[(size_t)m * G4 + n0 + tx * 4]       = r0;
        *(float4*)&g_xp[(size_t)(m + 1) * G4 + n0 + tx * 4] = r1;
    }
}

// ---------------- phase 2: persistent LSTM recurrence ----------------
// 128 CTAs x 256 threads (2 warps/SMSP). CTA owns 32 permuted cols (8 cells).
// Wh slice (1024x32 = 128KB) in SMEM; h chunks staged DUPLICATED so the
// f32x2 broadcast operand comes straight from one LDS.128 (no pack MOVs).
// Thread micro-tile: 2 batch x 4 cols (one full i/f/g/o quad), c in registers.
__global__ __launch_bounds__(NTHR, 1)
void lstm_persistent(const float* __restrict__ init_c,
                     const float* __restrict__ init_h,
                     const int*   __restrict__ lengths,
                     float* __restrict__ out) {
    extern __shared__ float smem[];
    float* ws = smem;                      // [1024][32]  Wh slice (128KB)
    float* hs = smem + H_ * COLS_PER_CTA;  // [2][64][128] duplicated h (64KB)

    const int tid = threadIdx.x;
    const int n0  = blockIdx.x * COLS_PER_CTA;
    const int tx  = tid & 7;       // col quad: n = n0 + tx*4
    const int ty  = tid >> 3;      // 0..31
    const int hc  = (n0 >> 2) + tx;
    const int b0  = ty * 2;        // batch pair b0, b0+1

    // ---- load Wh slice into SMEM (once) ----
    #pragma unroll 4
    for (int i = 0; i < 32; ++i) {
        int idx = i * NTHR + tid;          // float4 index, 0..8191
        int k  = idx >> 3;
        int c4 = (idx & 7) * 4;
        *(float4*)&ws[k * COLS_PER_CTA + c4] =
            *(const float4*)&g_Whp[(size_t)k * G4 + n0 + c4];
    }

    // ---- init own h slice (transposed) + private c registers ----
    float creg[2];
    {
        float h0 = init_h[(b0 + 0) * H_ + hc];
        float h1 = init_h[(b0 + 1) * H_ + hc];
        creg[0]  = init_c[(b0 + 0) * H_ + hc];
        creg[1]  = init_c[(b0 + 1) * H_ + hc];
        *(float2*)&g_hT[0][hc * B_ + b0] = make_float2(h0, h1);
    }
    int rl[2];
    rl[0] = lengths[b0 + 0];
    rl[1] = lengths[b0 + 1];

    const size_t fc_off = (size_t)B_ * T_ * H_;
    const size_t fh_off = fc_off + (size_t)B_ * H_;
    volatile unsigned* vbar = &g_bar;

    for (int t = 0; t < T_; ++t) {
        const float* __restrict__ hbuf = g_hT[t & 1];
        float* __restrict__ hnext = g_hT[(t + 1) & 1];

        // ---- grid barrier: all h writes for step t-1 (or init) visible ----
        __syncthreads();
        if (tid == 0) {
            __threadfence();
            atomicAdd(&g_bar, 1u);
            unsigned target = (unsigned)NCTA * (unsigned)(t + 1);
            while (*vbar < target) { }
            __threadfence();
        }
        __syncthreads();

        // ---- prefetch xp quads for this step ----
        float4 xp0 = *(const float4*)&g_xp[((size_t)(b0 + 0) * T_ + t) * G4 + n0 + tx * 4];
        float4 xp1 = *(const float4*)&g_xp[((size_t)(b0 + 1) * T_ + t) * G4 + n0 + tx * 4];

        ull acc00 = 0ULL, acc01 = 0ULL, acc10 = 0ULL, acc11 = 0ULL;

        // ---- stage chunk 0 (duplicated) ----
        float4 stg[4];
        #pragma unroll
        for (int q = 0; q < 4; ++q)
            stg[q] = __ldcg((const float4*)(hbuf) + q * NTHR + tid);
        #pragma unroll
        for (int q = 0; q < 4; ++q) {
            int fidx = q * NTHR + tid;          // float4 idx in source chunk
            int k  = fidx >> 4;
            int bb = (fidx & 15) * 4;
            float4 v = stg[q];
            *(float4*)&hs[k * HS_DUP + 2 * bb]     = make_float4(v.x, v.x, v.y, v.y);
            *(float4*)&hs[k * HS_DUP + 2 * bb + 4] = make_float4(v.z, v.z, v.w, v.w);
        }
        __syncthreads();

        for (int ch = 0; ch < NCHUNK; ++ch) {
            if (ch < NCHUNK - 1) {
                const float4* src = (const float4*)(hbuf + (ch + 1) * KCHUNK * B_);
                #pragma unroll
                for (int q = 0; q < 4; ++q) stg[q] = __ldcg(src + q * NTHR + tid);
            }
            const float* hcur = hs + (ch & 1) * HS_ELEMS;
            const float* wcur = ws + ch * KCHUNK * COLS_PER_CTA;
            #pragma unroll 8
            for (int kk = 0; kk < KCHUNK; ++kk) {
                ulonglong2 hp = *(const ulonglong2*)(hcur + kk * HS_DUP + 2 * b0);
                ulonglong2 wp = *(const ulonglong2*)(wcur + kk * COLS_PER_CTA + tx * 4);
                fma2(acc00, hp.x, wp.x); fma2(acc01, hp.x, wp.y);
                fma2(acc10, hp.y, wp.x); fma2(acc11, hp.y, wp.y);
            }
            if (ch < NCHUNK - 1) {
                float* dstb = hs + ((ch + 1) & 1) * HS_ELEMS;
                #pragma unroll
                for (int q = 0; q < 4; ++q) {
                    int fidx = q * NTHR + tid;
                    int k  = fidx >> 4;
                    int bb = (fidx & 15) * 4;
                    float4 v = stg[q];
                    *(float4*)&dstb[k * HS_DUP + 2 * bb]     = make_float4(v.x, v.x, v.y, v.y);
                    *(float4*)&dstb[k * HS_DUP + 2 * bb + 4] = make_float4(v.z, v.z, v.w, v.w);
                }
            }
            __syncthreads();
        }

        // ---- epilogue: gates + state update for 2 (b, hc) cells ----
        float hres[2];
        {
            float zi, zf, zg, zo;
            // cell (b0)
            unpack2(acc00, zi, zf);
            unpack2(acc01, zg, zo);
            zi += xp0.x; zf += xp0.y; zg += xp0.z; zo += xp0.w;
            {
                float ig = sigmoidf_(zi);
                float fg = sigmoidf_(zf);
                float gg = tanhf(zg);
                float og = sigmoidf_(zo);
                float c = fg * creg[0] + ig * gg;
                float h = og * tanhf(c);
                creg[0] = c; hres[0] = h;
                out[((size_t)(b0 + 0) * T_ + t) * H_ + hc] = h;
                if (t == rl[0] - 1) {
                    out[fc_off + (b0 + 0) * H_ + hc] = c;
                    out[fh_off + (b0 + 0) * H_ + hc] = h;
                }
            }
            // cell (b0+1)
            unpack2(acc10, zi, zf);
            unpack2(acc11, zg, zo);
            zi += xp1.x; zf += xp1.y; zg += xp1.z; zo += xp1.w;
            {
                float ig = sigmoidf_(zi);
                float fg = sigmoidf_(zf);
                float gg = tanhf(zg);
                float og = sigmoidf_(zo);
                float c = fg * creg[1] + ig * gg;
                float h = og * tanhf(c);
                creg[1] = c; hres[1] = h;
                out[((size_t)(b0 + 1) * T_ + t) * H_ + hc] = h;
                if (t == rl[1] - 1) {
                    out[fc_off + (b0 + 1) * H_ + hc] = c;
                    out[fh_off + (b0 + 1) * H_ + hc] = h;
                }
            }
        }
        *(float2*)&hnext[hc * B_ + b0] = make_float2(hres[0], hres[1]);
    }
}

// ---------------- launch ----------------
extern "C" void kernel_launch(void* const* d_in, const int* in_sizes, int n_in,
                              void* d_out, int out_size) {
    const float* inputs  = (const float*)d_in[0];
    const int*   lengths = (const int*)  d_in[1];
    const float* init_c  = (const float*)d_in[2];
    const float* init_h  = (const float*)d_in[3];
    const float* Wi      = (const float*)d_in[4];
    const float* Wh      = (const float*)d_in[5];
    const float* b       = (const float*)d_in[6];
    float* out = (float*)d_out;

    const int smem_bytes = (H_ * COLS_PER_CTA + 2 * HS_ELEMS) * sizeof(float); // 192KB
    cudaFuncSetAttribute(lstm_persistent,
                         cudaFuncAttributeMaxDynamicSharedMemorySize, smem_bytes);

    permute_kernel<<<(D_ * G4) / 256, 256>>>(Wi, Wh, b);
    gemm_xproj<<<dim3(G4 / 64, (B_ * T_) / 128), 256>>>(inputs);
    lstm_persistent<<<NCTA, NTHR, smem_bytes>>>(init_c, init_h, lengths, out);
}

// round 6
// speedup vs baseline: 1.1187x; 1.1187x over previous
#include <cuda_runtime.h>
#include <math.h>

#define B_  64
#define T_  512
#define D_  1024
#define H_  1024
#define G4  4096   // 4*H

#define NCTA   256
#define NTHR   128
#define COLS_PER_CTA 16          // permuted gate columns per CTA (= 4 hidden cells)
#define KCHUNK 64
#define NCHUNK (H_ / KCHUNK)     // 16
#define HS_ELEMS (KCHUNK * B_)   // floats per ping-pong buffer (4096)

// ---------------- device-global scratch ----------------
__device__ float g_Wip[D_ * G4];              // permuted Wi
__device__ float g_Whp[H_ * G4];              // permuted Wh
__device__ float g_bp[G4];                    // permuted bias
__device__ float g_xp[(size_t)B_ * T_ * G4];  // x_proj [b*T+t][4H] permuted cols
__device__ float g_hT[2][H_ * B_];            // hidden state, TRANSPOSED [hc][b], double buffered
__device__ unsigned g_bar;                    // grid barrier counter

typedef unsigned long long ull;

// ---------------- packed f32x2 helpers ----------------
__device__ __forceinline__ ull pack2(float lo, float hi) {
    ull r; asm("mov.b64 %0, {%1, %2};" : "=l"(r) : "f"(lo), "f"(hi)); return r;
}
__device__ __forceinline__ void unpack2(ull v, float& lo, float& hi) {
    asm("mov.b64 {%0, %1}, %2;" : "=f"(lo), "=f"(hi) : "l"(v));
}
__device__ __forceinline__ void fma2(ull& d, ull a, ull b) {
    asm("fma.rn.f32x2 %0, %1, %2, %0;" : "+l"(d) : "l"(a), "l"(b));
}
__device__ __forceinline__ float sigmoidf_(float x) { return 1.0f / (1.0f + expf(-x)); }

// ---------------- phase 0: permute weights (gate-interleave columns) ----------
// new col n' = hc*4 + g  <-  old col g*1024 + hc
__global__ void permute_kernel(const float* __restrict__ Wi,
                               const float* __restrict__ Wh,
                               const float* __restrict__ b) {
    int idx = blockIdx.x * blockDim.x + threadIdx.x;   // 0 .. 4M-1
    int k  = idx >> 12;
    int np = idx & 4095;
    int hc = np >> 2;
    int gg = np & 3;
    int src = (k << 12) + (gg << 10) + hc;
    g_Wip[idx] = Wi[src];
    g_Whp[idx] = Wh[src];
    if (idx < G4) g_bp[idx] = b[((idx & 3) << 10) + (idx >> 2)];
    if (idx == 0) g_bar = 0u;
}

// ---------------- phase 1: x_proj = X @ Wip + bp (unchanged) ----------
__global__ __launch_bounds__(256)
void gemm_xproj(const float* __restrict__ X) {
    __shared__ float As[16][128];
    __shared__ float Bs[16][64];

    const int tid = threadIdx.x;
    const int m0 = blockIdx.y * 128;
    const int n0 = blockIdx.x * 64;
    const int tx = tid & 15;
    const int ty = tid >> 4;

    const int am = tid >> 1;
    const int ak = (tid & 1) * 4;
    const float* Aptr = X + (size_t)(m0 + am) * 1024 + ak;
    const int brow = tid >> 4;
    const int bcol = (tid & 15) * 4;
    const float* Bptr = g_Wip + (size_t)brow * G4 + n0 + bcol;

    float4 a0 = *(const float4*)(Aptr);
    float4 a1 = *(const float4*)(Aptr + 8);
    float4 bv = *(const float4*)(Bptr);

    ull acc[4][4];
    #pragma unroll
    for (int i = 0; i < 4; ++i)
        #pragma unroll
        for (int j = 0; j < 4; ++j) acc[i][j] = 0ULL;

    for (int kt = 0; kt < 64; ++kt) {
        As[ak + 0][am] = a0.x; As[ak + 1][am] = a0.y;
        As[ak + 2][am] = a0.z; As[ak + 3][am] = a0.w;
        As[ak + 8][am] = a1.x; As[ak + 9][am] = a1.y;
        As[ak +10][am] = a1.z; As[ak +11][am] = a1.w;
        *(float4*)&Bs[brow][bcol] = bv;
        __syncthreads();

        if (kt < 63) {
            Aptr += 16;
            Bptr += (size_t)16 * G4;
            a0 = *(const float4*)(Aptr);
            a1 = *(const float4*)(Aptr + 8);
            bv = *(const float4*)(Bptr);
        }

        #pragma unroll
        for (int k = 0; k < 16; ++k) {
            const ulonglong2* ap = (const ulonglong2*)&As[k][ty * 8];
            ulonglong2 A0 = ap[0];
            ulonglong2 A1 = ap[1];
            float4 b4 = *(const float4*)&Bs[k][tx * 4];
            ull bp0 = pack2(b4.x, b4.x);
            ull bp1 = pack2(b4.y, b4.y);
            ull bp2 = pack2(b4.z, b4.z);
            ull bp3 = pack2(b4.w, b4.w);
            fma2(acc[0][0], A0.x, bp0); fma2(acc[0][1], A0.x, bp1);
            fma2(acc[0][2], A0.x, bp2); fma2(acc[0][3], A0.x, bp3);
            fma2(acc[1][0], A0.y, bp0); fma2(acc[1][1], A0.y, bp1);
            fma2(acc[1][2], A0.y, bp2); fma2(acc[1][3], A0.y, bp3);
            fma2(acc[2][0], A1.x, bp0); fma2(acc[2][1], A1.x, bp1);
            fma2(acc[2][2], A1.x, bp2); fma2(acc[2][3], A1.x, bp3);
            fma2(acc[3][0], A1.y, bp0); fma2(acc[3][1], A1.y, bp1);
            fma2(acc[3][2], A1.y, bp2); fma2(acc[3][3], A1.y, bp3);
        }
        __syncthreads();
    }

    float4 bias = *(const float4*)(g_bp + n0 + tx * 4);
    #pragma unroll
    for (int mp = 0; mp < 4; ++mp) {
        float lo0, hi0, lo1, hi1, lo2, hi2, lo3, hi3;
        unpack2(acc[mp][0], lo0, hi0);
        unpack2(acc[mp][1], lo1, hi1);
        unpack2(acc[mp][2], lo2, hi2);
        unpack2(acc[mp][3], lo3, hi3);
        int m = m0 + ty * 8 + mp * 2;
        float4 r0 = make_float4(lo0 + bias.x, lo1 + bias.y, lo2 + bias.z, lo3 + bias.w);
        float4 r1 = make_float4(hi0 + bias.x, hi1 + bias.y, hi2 + bias.z, hi3 + bias.w);
        *(float4*)&g_xp[(size_t)m * G4 + n0 + tx * 4]       = r0;
        *(float4*)&g_xp[(size_t)(m + 1) * G4 + n0 + tx * 4] = r1;
    }
}

// ---------------- phase 2: persistent LSTM recurrence ----------------
// 256 CTAs x 128 threads, 2 CTAs per SM (the 2nd warp per SMSP comes from an
// INDEPENDENT CTA -> real latency hiding, no intra-CTA warp-pair serialization).
// CTA owns 16 permuted cols (4 cells). Wh slice 64KB + h ping-pong 32KB = 96KB.
// Thread micro-tile: 2 batch x 4 cols (one full i/f/g/o quad), c in registers.
__global__ __launch_bounds__(NTHR, 2)
void lstm_persistent(const float* __restrict__ init_c,
                     const float* __restrict__ init_h,
                     const int*   __restrict__ lengths,
                     float* __restrict__ out) {
    extern __shared__ float smem[];
    float* ws = smem;                      // [1024][16]  Wh slice (64KB)
    float* hs = smem + H_ * COLS_PER_CTA;  // [2][64][64] h chunk ping-pong (32KB)

    const int tid = threadIdx.x;
    const int n0  = blockIdx.x * COLS_PER_CTA;
    const int tx  = tid & 3;       // col quad: n = n0 + tx*4
    const int ty  = tid >> 2;      // 0..31
    const int hc  = (n0 >> 2) + tx;
    const int b0  = ty * 2;        // batch pair b0, b0+1

    // ---- load Wh slice into SMEM (once): 1024x16 floats = 4096 float4 ----
    #pragma unroll 4
    for (int i = 0; i < 32; ++i) {
        int idx = i * NTHR + tid;          // float4 index, 0..4095
        int k  = idx >> 2;
        int c4 = (idx & 3) * 4;
        *(float4*)&ws[k * COLS_PER_CTA + c4] =
            *(const float4*)&g_Whp[(size_t)k * G4 + n0 + c4];
    }

    // ---- init own h slice (transposed) + private c registers ----
    float creg[2];
    {
        float h0 = init_h[(b0 + 0) * H_ + hc];
        float h1 = init_h[(b0 + 1) * H_ + hc];
        creg[0]  = init_c[(b0 + 0) * H_ + hc];
        creg[1]  = init_c[(b0 + 1) * H_ + hc];
        *(float2*)&g_hT[0][hc * B_ + b0] = make_float2(h0, h1);
    }
    int rl[2];
    rl[0] = lengths[b0 + 0];
    rl[1] = lengths[b0 + 1];

    const size_t fc_off = (size_t)B_ * T_ * H_;
    const size_t fh_off = fc_off + (size_t)B_ * H_;
    volatile unsigned* vbar = &g_bar;

    for (int t = 0; t < T_; ++t) {
        const float* __restrict__ hbuf = g_hT[t & 1];
        float* __restrict__ hnext = g_hT[(t + 1) & 1];

        // ---- grid barrier: all h writes for step t-1 (or init) visible ----
        __syncthreads();
        if (tid == 0) {
            __threadfence();
            atomicAdd(&g_bar, 1u);
            unsigned target = (unsigned)NCTA * (unsigned)(t + 1);
            while (*vbar < target) { }
            __threadfence();
        }
        __syncthreads();

        // ---- prefetch xp quads for this step ----
        float4 xp0 = *(const float4*)&g_xp[((size_t)(b0 + 0) * T_ + t) * G4 + n0 + tx * 4];
        float4 xp1 = *(const float4*)&g_xp[((size_t)(b0 + 1) * T_ + t) * G4 + n0 + tx * 4];

        ull acc00 = 0ULL, acc01 = 0ULL, acc10 = 0ULL, acc11 = 0ULL;

        // ---- stage chunk 0: 64k x 64b = 1024 float4, 8 per thread ----
        float4 stg[8];
        #pragma unroll
        for (int q = 0; q < 8; ++q)
            stg[q] = __ldcg((const float4*)(hbuf) + q * NTHR + tid);
        #pragma unroll
        for (int q = 0; q < 8; ++q)
            *((float4*)hs + q * NTHR + tid) = stg[q];
        __syncthreads();

        for (int ch = 0; ch < NCHUNK; ++ch) {
            if (ch < NCHUNK - 1) {
                const float4* src = (const float4*)(hbuf + (ch + 1) * HS_ELEMS);
                #pragma unroll
                for (int q = 0; q < 8; ++q) stg[q] = __ldcg(src + q * NTHR + tid);
            }
            const float* hcur = hs + (ch & 1) * HS_ELEMS;
            const float* wcur = ws + ch * KCHUNK * COLS_PER_CTA;
            #pragma unroll 8
            for (int kk = 0; kk < KCHUNK; ++kk) {
                float2 h2 = *(const float2*)(hcur + kk * B_ + b0);
                ulonglong2 wp = *(const ulonglong2*)(wcur + kk * COLS_PER_CTA + tx * 4);
                ull hp0 = pack2(h2.x, h2.x);
                ull hp1 = pack2(h2.y, h2.y);
                fma2(acc00, hp0, wp.x); fma2(acc01, hp0, wp.y);
                fma2(acc10, hp1, wp.x); fma2(acc11, hp1, wp.y);
            }
            if (ch < NCHUNK - 1) {
                float4* dst = (float4*)(hs + ((ch + 1) & 1) * HS_ELEMS);
                #pragma unroll
                for (int q = 0; q < 8; ++q) dst[q * NTHR + tid] = stg[q];
            }
            __syncthreads();
        }

        // ---- epilogue: gates + state update for 2 (b, hc) cells ----
        float hres[2];
        {
            float zi, zf, zg, zo;
            // cell (b0)
            unpack2(acc00, zi, zf);
            unpack2(acc01, zg, zo);
            zi += xp0.x; zf += xp0.y; zg += xp0.z; zo += xp0.w;
            {
                float ig = sigmoidf_(zi);
                float fg = sigmoidf_(zf);
                float gg = tanhf(zg);
                float og = sigmoidf_(zo);
                float c = fg * creg[0] + ig * gg;
                float h = og * tanhf(c);
                creg[0] = c; hres[0] = h;
                out[((size_t)(b0 + 0) * T_ + t) * H_ + hc] = h;
                if (t == rl[0] - 1) {
                    out[fc_off + (b0 + 0) * H_ + hc] = c;
                    out[fh_off + (b0 + 0) * H_ + hc] = h;
                }
            }
            // cell (b0+1)
            unpack2(acc10, zi, zf);
            unpack2(acc11, zg, zo);
            zi += xp1.x; zf += xp1.y; zg += xp1.z; zo += xp1.w;
            {
                float ig = sigmoidf_(zi);
                float fg = sigmoidf_(zf);
                float gg = tanhf(zg);
                float og = sigmoidf_(zo);
                float c = fg * creg[1] + ig * gg;
                float h = og * tanhf(c);
                creg[1] = c; hres[1] = h;
                out[((size_t)(b0 + 1) * T_ + t) * H_ + hc] = h;
                if (t == rl[1] - 1) {
                    out[fc_off + (b0 + 1) * H_ + hc] = c;
                    out[fh_off + (b0 + 1) * H_ + hc] = h;
                }
            }
        }
        *(float2*)&hnext[hc * B_ + b0] = make_float2(hres[0], hres[1]);
    }
}

// ---------------- launch ----------------
extern "C" void kernel_launch(void* const* d_in, const int* in_sizes, int n_in,
                              void* d_out, int out_size) {
    const float* inputs  = (const float*)d_in[0];
    const int*   lengths = (const int*)  d_in[1];
    const float* init_c  = (const float*)d_in[2];
    const float* init_h  = (const float*)d_in[3];
    const float* Wi      = (const float*)d_in[4];
    const float* Wh      = (const float*)d_in[5];
    const float* b       = (const float*)d_in[6];
    float* out = (float*)d_out;

    const int smem_bytes = (H_ * COLS_PER_CTA + 2 * HS_ELEMS) * sizeof(float); // 96KB
    cudaFuncSetAttribute(lstm_persistent,
                         cudaFuncAttributeMaxDynamicSharedMemorySize, smem_bytes);

    permute_kernel<<<(D_ * G4) / 256, 256>>>(Wi, Wh, b);
    gemm_xproj<<<dim3(G4 / 64, (B_ * T_) / 128), 256>>>(inputs);
    lstm_persistent<<<NCTA, NTHR, smem_bytes>>>(init_c, init_h, lengths, out);
}

// round 7
// speedup vs baseline: 1.1274x; 1.0078x over previous
#include <cuda_runtime.h>
#include <math.h>

#define B_  64
#define T_  512
#define D_  1024
#define H_  1024
#define G4  4096   // 4*H

#define NCTA   128
#define NTHR   128
#define COLS_PER_CTA 32          // permuted gate columns per CTA (= 8 hidden cells)
#define KCHUNK 64
#define NCHUNK (H_ / KCHUNK)     // 16
#define HS_DUP (2 * B_)          // duplicated batch width (128)
#define HS_ELEMS (KCHUNK * HS_DUP)   // floats per ping-pong buffer (8192)

// ---------------- device-global scratch ----------------
__device__ float g_Wip[D_ * G4];              // permuted Wi
__device__ float g_Whp[H_ * G4];              // permuted Wh
__device__ float g_bp[G4];                    // permuted bias
__device__ float g_xp[(size_t)B_ * T_ * G4];  // x_proj [b*T+t][4H] permuted cols
__device__ float g_hT[2][H_ * B_];            // hidden state, TRANSPOSED [hc][b], double buffered
__device__ unsigned g_bar;                    // grid barrier counter

typedef unsigned long long ull;

// ---------------- packed f32x2 helpers ----------------
__device__ __forceinline__ ull pack2(float lo, float hi) {
    ull r; asm("mov.b64 %0, {%1, %2};" : "=l"(r) : "f"(lo), "f"(hi)); return r;
}
__device__ __forceinline__ void unpack2(ull v, float& lo, float& hi) {
    asm("mov.b64 {%0, %1}, %2;" : "=f"(lo), "=f"(hi) : "l"(v));
}
__device__ __forceinline__ void fma2(ull& d, ull a, ull b) {
    asm("fma.rn.f32x2 %0, %1, %2, %0;" : "+l"(d) : "l"(a), "l"(b));
}
__device__ __forceinline__ float sigmoidf_(float x) { return 1.0f / (1.0f + expf(-x)); }

// ---------------- phase 0: permute weights (gate-interleave columns) ----------
// new col n' = hc*4 + g  <-  old col g*1024 + hc
__global__ void permute_kernel(const float* __restrict__ Wi,
                               const float* __restrict__ Wh,
                               const float* __restrict__ b) {
    int idx = blockIdx.x * blockDim.x + threadIdx.x;   // 0 .. 4M-1
    int k  = idx >> 12;
    int np = idx & 4095;
    int hc = np >> 2;
    int gg = np & 3;
    int src = (k << 12) + (gg << 10) + hc;
    g_Wip[idx] = Wi[src];
    g_Whp[idx] = Wh[src];
    if (idx < G4) g_bp[idx] = b[((idx & 3) << 10) + (idx >> 2)];
    if (idx == 0) g_bar = 0u;
}

// ---------------- phase 1: x_proj = X @ Wip + bp (unchanged) ----------
__global__ __launch_bounds__(256)
void gemm_xproj(const float* __restrict__ X) {
    __shared__ float As[16][128];
    __shared__ float Bs[16][64];

    const int tid = threadIdx.x;
    const int m0 = blockIdx.y * 128;
    const int n0 = blockIdx.x * 64;
    const int tx = tid & 15;
    const int ty = tid >> 4;

    const int am = tid >> 1;
    const int ak = (tid & 1) * 4;
    const float* Aptr = X + (size_t)(m0 + am) * 1024 + ak;
    const int brow = tid >> 4;
    const int bcol = (tid & 15) * 4;
    const float* Bptr = g_Wip + (size_t)brow * G4 + n0 + bcol;

    float4 a0 = *(const float4*)(Aptr);
    float4 a1 = *(const float4*)(Aptr + 8);
    float4 bv = *(const float4*)(Bptr);

    ull acc[4][4];
    #pragma unroll
    for (int i = 0; i < 4; ++i)
        #pragma unroll
        for (int j = 0; j < 4; ++j) acc[i][j] = 0ULL;

    for (int kt = 0; kt < 64; ++kt) {
        As[ak + 0][am] = a0.x; As[ak + 1][am] = a0.y;
        As[ak + 2][am] = a0.z; As[ak + 3][am] = a0.w;
        As[ak + 8][am] = a1.x; As[ak + 9][am] = a1.y;
        As[ak +10][am] = a1.z; As[ak +11][am] = a1.w;
        *(float4*)&Bs[brow][bcol] = bv;
        __syncthreads();

        if (kt < 63) {
            Aptr += 16;
            Bptr += (size_t)16 * G4;
            a0 = *(const float4*)(Aptr);
            a1 = *(const float4*)(Aptr + 8);
            bv = *(const float4*)(Bptr);
        }

        #pragma unroll
        for (int k = 0; k < 16; ++k) {
            const ulonglong2* ap = (const ulonglong2*)&As[k][ty * 8];
            ulonglong2 A0 = ap[0];
            ulonglong2 A1 = ap[1];
            float4 b4 = *(const float4*)&Bs[k][tx * 4];
            ull bp0 = pack2(b4.x, b4.x);
            ull bp1 = pack2(b4.y, b4.y);
            ull bp2 = pack2(b4.z, b4.z);
            ull bp3 = pack2(b4.w, b4.w);
            fma2(acc[0][0], A0.x, bp0); fma2(acc[0][1], A0.x, bp1);
            fma2(acc[0][2], A0.x, bp2); fma2(acc[0][3], A0.x, bp3);
            fma2(acc[1][0], A0.y, bp0); fma2(acc[1][1], A0.y, bp1);
            fma2(acc[1][2], A0.y, bp2); fma2(acc[1][3], A0.y, bp3);
            fma2(acc[2][0], A1.x, bp0); fma2(acc[2][1], A1.x, bp1);
            fma2(acc[2][2], A1.x, bp2); fma2(acc[2][3], A1.x, bp3);
            fma2(acc[3][0], A1.y, bp0); fma2(acc[3][1], A1.y, bp1);
            fma2(acc[3][2], A1.y, bp2); fma2(acc[3][3], A1.y, bp3);
        }
        __syncthreads();
    }

    float4 bias = *(const float4*)(g_bp + n0 + tx * 4);
    #pragma unroll
    for (int mp = 0; mp < 4; ++mp) {
        float lo0, hi0, lo1, hi1, lo2, hi2, lo3, hi3;
        unpack2(acc[mp][0], lo0, hi0);
        unpack2(acc[mp][1], lo1, hi1);
        unpack2(acc[mp][2], lo2, hi2);
        unpack2(acc[mp][3], lo3, hi3);
        int m = m0 + ty * 8 + mp * 2;
        float4 r0 = make_float4(lo0 + bias.x, lo1 + bias.y, lo2 + bias.z, lo3 + bias.w);
        float4 r1 = make_float4(hi0 + bias.x, hi1 + bias.y, hi2 + bias.z, hi3 + bias.w);
        *(float4*)&g_xp[(size_t)m * G4 + n0 + tx * 4]       = r0;
        *(float4*)&g_xp[(size_t)(m + 1) * G4 + n0 + tx * 4] = r1;
    }
}

// ---------------- phase 2: persistent LSTM recurrence ----------------
// 128 CTAs x 128 threads, 1 CTA/SM (R2 topology — the proven best).
// NEW vs R2: h staged DUPLICATED in SMEM (hs[k][2b]=hs[k][2b+1]=h_b) so the
// inner loop is 3x LDS.128 + 8x FFMA2 per k-iter with NO pack MOVs — FFMA2
// consumes LDS results directly, enabling deep software pipelining.
// Thread micro-tile: 4 batch x 4 cols (one full i/f/g/o quad), c in registers.
__global__ __launch_bounds__(NTHR, 1)
void lstm_persistent(const float* __restrict__ init_c,
                     const float* __restrict__ init_h,
                     const int*   __restrict__ lengths,
                     float* __restrict__ out) {
    extern __shared__ float smem[];
    float* ws = smem;                      // [1024][32]  Wh slice (128KB)
    float* hs = smem + H_ * COLS_PER_CTA;  // [2][64][128] duplicated h (64KB)

    const int tid = threadIdx.x;
    const int n0  = blockIdx.x * COLS_PER_CTA;
    const int tx  = tid & 7;       // col quad: n = n0 + tx*4
    const int ty  = tid >> 3;      // 0..15
    const int hc  = (n0 >> 2) + tx;
    const int b0  = ty * 4;        // batches b0 .. b0+3

    // ---- load Wh slice into SMEM (once): 1024x32 floats = 8192 float4 ----
    #pragma unroll 4
    for (int i = 0; i < 64; ++i) {
        int idx = i * NTHR + tid;          // float4 index, 0..8191
        int k  = idx >> 3;
        int c4 = (idx & 7) * 4;
        *(float4*)&ws[k * COLS_PER_CTA + c4] =
            *(const float4*)&g_Whp[(size_t)k * G4 + n0 + c4];
    }

    // ---- init own h slice (transposed) + private c registers ----
    float creg[4];
    {
        float tmp[4];
        #pragma unroll
        for (int j = 0; j < 4; ++j) {
            creg[j] = init_c[(b0 + j) * H_ + hc];
            tmp[j]  = init_h[(b0 + j) * H_ + hc];
        }
        *(float4*)&g_hT[0][hc * B_ + b0] = make_float4(tmp[0], tmp[1], tmp[2], tmp[3]);
    }
    int rl[4];
    #pragma unroll
    for (int j = 0; j < 4; ++j) rl[j] = lengths[b0 + j];

    const size_t fc_off = (size_t)B_ * T_ * H_;
    const size_t fh_off = fc_off + (size_t)B_ * H_;
    volatile unsigned* vbar = &g_bar;

    for (int t = 0; t < T_; ++t) {
        const float* __restrict__ hbuf = g_hT[t & 1];
        float* __restrict__ hnext = g_hT[(t + 1) & 1];

        // ---- prefetch xp quads for this step (independent of h -> before barrier) ----
        float4 xpv[4];
        #pragma unroll
        for (int j = 0; j < 4; ++j)
            xpv[j] = __ldg((const float4*)&g_xp[((size_t)(b0 + j) * T_ + t) * G4 + n0 + tx * 4]);

        // ---- grid barrier: all h writes for step t-1 (or init) visible ----
        __syncthreads();
        if (tid == 0) {
            __threadfence();
            atomicAdd(&g_bar, 1u);
            unsigned target = (unsigned)NCTA * (unsigned)(t + 1);
            while (*vbar < target) { }
            __threadfence();
        }
        __syncthreads();

        // acc[b][0] = (z_i, z_f), acc[b][1] = (z_g, z_o)
        ull acc[4][2];
        #pragma unroll
        for (int j = 0; j < 4; ++j) { acc[j][0] = 0ULL; acc[j][1] = 0ULL; }

        // ---- stage chunk 0 duplicated: src 4096 floats -> 8192 dup ----
        float4 stg[8];
        #pragma unroll
        for (int q = 0; q < 8; ++q)
            stg[q] = __ldcg((const float4*)(hbuf) + q * NTHR + tid);
        #pragma unroll
        for (int q = 0; q < 8; ++q) {
            int fidx = q * NTHR + tid;          // source float4 idx (0..1023)
            int k  = fidx >> 4;                 // 0..63
            int bb = (fidx & 15) * 4;           // source batch base
            float4 v = stg[q];
            *(float4*)&hs[k * HS_DUP + 2 * bb]     = make_float4(v.x, v.x, v.y, v.y);
            *(float4*)&hs[k * HS_DUP + 2 * bb + 4] = make_float4(v.z, v.z, v.w, v.w);
        }
        __syncthreads();

        for (int ch = 0; ch < NCHUNK; ++ch) {
            if (ch < NCHUNK - 1) {
                const float4* src = (const float4*)(hbuf + (ch + 1) * KCHUNK * B_);
                #pragma unroll
                for (int q = 0; q < 8; ++q) stg[q] = __ldcg(src + q * NTHR + tid);
            }
            const float* hcur = hs + (ch & 1) * HS_ELEMS;
            const float* wcur = ws + ch * KCHUNK * COLS_PER_CTA;
            #pragma unroll 8
            for (int kk = 0; kk < KCHUNK; ++kk) {
                // duplicated h: (h_b0,h_b0,h_b1,h_b1) and (h_b2,h_b2,h_b3,h_b3)
                ulonglong2 hA = *(const ulonglong2*)(hcur + kk * HS_DUP + 2 * b0);
                ulonglong2 hB = *(const ulonglong2*)(hcur + kk * HS_DUP + 2 * b0 + 4);
                // weights quad as two f32x2: (w_i,w_f),(w_g,w_o)
                ulonglong2 wp = *(const ulonglong2*)(wcur + kk * COLS_PER_CTA + tx * 4);
                fma2(acc[0][0], hA.x, wp.x); fma2(acc[0][1], hA.x, wp.y);
                fma2(acc[1][0], hA.y, wp.x); fma2(acc[1][1], hA.y, wp.y);
                fma2(acc[2][0], hB.x, wp.x); fma2(acc[2][1], hB.x, wp.y);
                fma2(acc[3][0], hB.y, wp.x); fma2(acc[3][1], hB.y, wp.y);
            }
            if (ch < NCHUNK - 1) {
                float* dstb = hs + ((ch + 1) & 1) * HS_ELEMS;
                #pragma unroll
                for (int q = 0; q < 8; ++q) {
                    int fidx = q * NTHR + tid;
                    int k  = fidx >> 4;
                    int bb = (fidx & 15) * 4;
                    float4 v = stg[q];
                    *(float4*)&dstb[k * HS_DUP + 2 * bb]     = make_float4(v.x, v.x, v.y, v.y);
                    *(float4*)&dstb[k * HS_DUP + 2 * bb + 4] = make_float4(v.z, v.z, v.w, v.w);
                }
            }
            __syncthreads();
        }

        // ---- epilogue: gates + state update for 4 (b, hc) cells ----
        float hres[4];
        #pragma unroll
        for (int j = 0; j < 4; ++j) {
            float zi, zf, zg, zo;
            unpack2(acc[j][0], zi, zf);
            unpack2(acc[j][1], zg, zo);
            zi += xpv[j].x; zf += xpv[j].y; zg += xpv[j].z; zo += xpv[j].w;
            float ig = sigmoidf_(zi);
            float fg = sigmoidf_(zf);
            float gg = tanhf(zg);
            float og = sigmoidf_(zo);
            float c = fg * creg[j] + ig * gg;
            float h = og * tanhf(c);
            creg[j] = c; hres[j] = h;
            out[((size_t)(b0 + j) * T_ + t) * H_ + hc] = h;
            if (t == rl[j] - 1) {
                out[fc_off + (b0 + j) * H_ + hc] = c;
                out[fh_off + (b0 + j) * H_ + hc] = h;
            }
        }
        *(float4*)&hnext[hc * B_ + b0] = make_float4(hres[0], hres[1], hres[2], hres[3]);
    }
}

// ---------------- launch ----------------
extern "C" void kernel_launch(void* const* d_in, const int* in_sizes, int n_in,
                              void* d_out, int out_size) {
    const float* inputs  = (const float*)d_in[0];
    const int*   lengths = (const int*)  d_in[1];
    const float* init_c  = (const float*)d_in[2];
    const float* init_h  = (const float*)d_in[3];
    const float* Wi      = (const float*)d_in[4];
    const float* Wh      = (const float*)d_in[5];
    const float* b       = (const float*)d_in[6];
    float* out = (float*)d_out;

    const int smem_bytes = (H_ * COLS_PER_CTA + 2 * HS_ELEMS) * sizeof(float); // 192KB
    cudaFuncSetAttribute(lstm_persistent,
                         cudaFuncAttributeMaxDynamicSharedMemorySize, smem_bytes);

    permute_kernel<<<(D_ * G4) / 256, 256>>>(Wi, Wh, b);
    gemm_xproj<<<dim3(G4 / 64, (B_ * T_) / 128), 256>>>(inputs);
    lstm_persistent<<<NCTA, NTHR, smem_bytes>>>(init_c, init_h, lengths, out);
}

// round 10
// speedup vs baseline: 2.0033x; 1.7768x over previous
#include <cuda_runtime.h>
#include <cuda_bf16.h>
#include <math.h>

#define B_  64
#define T_  512
#define D_  1024
#define H_  1024
#define G4  4096   // 4*H

#define NCTA   128
#define NTHR   128

// smem layout (halves): W^T hi [32][1032], W^T lo [32][1032], A hi [64][136], A lo [64][136]
#define WS_STRIDE 1032
#define AS_STRIDE 136
#define WS_HALVES (32 * WS_STRIDE)          // 33024
#define AS_HALVES (64 * AS_STRIDE)          // 8704
#define SMEM_HALVES (2 * WS_HALVES + 2 * AS_HALVES)
#define SMEM_BYTES  (SMEM_HALVES * 2)       // 166912

// ---------------- device-global scratch ----------------
__device__ float g_Wip[D_ * G4];                  // permuted Wi (fp32, for x_proj gemm)
__device__ float g_bp[G4];                        // permuted bias
__device__ float g_xp[(size_t)B_ * T_ * G4];      // x_proj [b*T+t][4H] permuted cols
__device__ __nv_bfloat16 g_WtHi[(size_t)G4 * H_]; // Wh^T permuted [np][k], bf16 hi
__device__ __nv_bfloat16 g_WtLo[(size_t)G4 * H_]; // bf16 lo
__device__ __nv_bfloat16 g_hbf[2][2][B_ * H_];    // [buf][hi/lo][b][k] hidden state bf16 split
__device__ unsigned g_bar;                        // grid barrier counter

typedef unsigned long long ull;
typedef unsigned int u32;

// ---------------- packed f32x2 helpers (for fp32 x_proj gemm) ----------------
__device__ __forceinline__ ull pack2(float lo, float hi) {
    ull r; asm("mov.b64 %0, {%1, %2};" : "=l"(r) : "f"(lo), "f"(hi)); return r;
}
__device__ __forceinline__ void unpack2(ull v, float& lo, float& hi) {
    asm("mov.b64 {%0, %1}, %2;" : "=f"(lo), "=f"(hi) : "l"(v));
}
__device__ __forceinline__ void fma2(ull& d, ull a, ull b) {
    asm("fma.rn.f32x2 %0, %1, %2, %0;" : "+l"(d) : "l"(a), "l"(b));
}
__device__ __forceinline__ float sigmoidf_(float x) { return 1.0f / (1.0f + expf(-x)); }

__device__ __forceinline__ u32 su32(const void* p) {
    return (u32)__cvta_generic_to_shared(p);
}

#define LDSM4(r0, r1, r2, r3, addr) \
    asm volatile("ldmatrix.sync.aligned.m8n8.x4.shared.b16 {%0,%1,%2,%3}, [%4];" \
                 : "=r"(r0), "=r"(r1), "=r"(r2), "=r"(r3) : "r"(addr))

#define MMA_BF16(d, a, b0r, b1r) \
    asm volatile("mma.sync.aligned.m16n8k16.row.col.f32.bf16.bf16.f32 " \
                 "{%0,%1,%2,%3},{%4,%5,%6,%7},{%8,%9},{%0,%1,%2,%3};" \
                 : "+f"(d[0]), "+f"(d[1]), "+f"(d[2]), "+f"(d[3]) \
                 : "r"(a[0]), "r"(a[1]), "r"(a[2]), "r"(a[3]), "r"(b0r), "r"(b1r))

// ---------------- phase 0a: permute Wi + bias (fp32) ----------------
// new col n' = hc*4 + g  <-  old col g*1024 + hc
__global__ void permute_kernel(const float* __restrict__ Wi,
                               const float* __restrict__ b) {
    int idx = blockIdx.x * blockDim.x + threadIdx.x;   // 0 .. 4M-1
    int k  = idx >> 12;
    int np = idx & 4095;
    int src = (k << 12) + ((np & 3) << 10) + (np >> 2);
    g_Wip[idx] = Wi[src];
    if (idx < G4) g_bp[idx] = b[((idx & 3) << 10) + (idx >> 2)];
    if (idx == 0) g_bar = 0u;
}

// ---------------- phase 0b: Wh -> permuted transposed bf16 split ----------------
// g_Wt[np][k] = Wh[k][ (np&3)*1024 + (np>>2) ], split into bf16 hi + lo
__global__ void wsplit_kernel(const float* __restrict__ Wh) {
    int idx = blockIdx.x * blockDim.x + threadIdx.x;   // 0 .. 4M-1
    int np = idx >> 10;
    int k  = idx & 1023;
    float w = Wh[(size_t)k * G4 + ((np & 3) << 10) + (np >> 2)];
    __nv_bfloat16 hi = __float2bfloat16(w);
    g_WtHi[idx] = hi;
    g_WtLo[idx] = __float2bfloat16(w - __bfloat162float(hi));
}

// ---------------- phase 0c: init h (bf16 split) ----------------
__global__ void init_state(const float* __restrict__ init_h) {
    int idx = blockIdx.x * blockDim.x + threadIdx.x;   // 0 .. 65535
    float v = init_h[idx];
    __nv_bfloat16 hi = __float2bfloat16(v);
    g_hbf[0][0][idx] = hi;
    g_hbf[0][1][idx] = __float2bfloat16(v - __bfloat162float(hi));
}

// ---------------- phase 1: x_proj = X @ Wip + bp (unchanged fp32) ----------
__global__ __launch_bounds__(256)
void gemm_xproj(const float* __restrict__ X) {
    __shared__ float As[16][128];
    __shared__ float Bs[16][64];

    const int tid = threadIdx.x;
    const int m0 = blockIdx.y * 128;
    const int n0 = blockIdx.x * 64;
    const int tx = tid & 15;
    const int ty = tid >> 4;

    const int am = tid >> 1;
    const int ak = (tid & 1) * 4;
    const float* Aptr = X + (size_t)(m0 + am) * 1024 + ak;
    const int brow = tid >> 4;
    const int bcol = (tid & 15) * 4;
    const float* Bptr = g_Wip + (size_t)brow * G4 + n0 + bcol;

    float4 a0 = *(const float4*)(Aptr);
    float4 a1 = *(const float4*)(Aptr + 8);
    float4 bv = *(const float4*)(Bptr);

    ull acc[4][4];
    #pragma unroll
    for (int i = 0; i < 4; ++i)
        #pragma unroll
        for (int j = 0; j < 4; ++j) acc[i][j] = 0ULL;

    for (int kt = 0; kt < 64; ++kt) {
        As[ak + 0][am] = a0.x; As[ak + 1][am] = a0.y;
        As[ak + 2][am] = a0.z; As[ak + 3][am] = a0.w;
        As[ak + 8][am] = a1.x; As[ak + 9][am] = a1.y;
        As[ak +10][am] = a1.z; As[ak +11][am] = a1.w;
        *(float4*)&Bs[brow][bcol] = bv;
        __syncthreads();

        if (kt < 63) {
            Aptr += 16;
            Bptr += (size_t)16 * G4;
            a0 = *(const float4*)(Aptr);
            a1 = *(const float4*)(Aptr + 8);
            bv = *(const float4*)(Bptr);
        }

        #pragma unroll
        for (int k = 0; k < 16; ++k) {
            const ulonglong2* ap = (const ulonglong2*)&As[k][ty * 8];
            ulonglong2 A0 = ap[0];
            ulonglong2 A1 = ap[1];
            float4 b4 = *(const float4*)&Bs[k][tx * 4];
            ull bp0 = pack2(b4.x, b4.x);
            ull bp1 = pack2(b4.y, b4.y);
            ull bp2 = pack2(b4.z, b4.z);
            ull bp3 = pack2(b4.w, b4.w);
            fma2(acc[0][0], A0.x, bp0); fma2(acc[0][1], A0.x, bp1);
            fma2(acc[0][2], A0.x, bp2); fma2(acc[0][3], A0.x, bp3);
            fma2(acc[1][0], A0.y, bp0); fma2(acc[1][1], A0.y, bp1);
            fma2(acc[1][2], A0.y, bp2); fma2(acc[1][3], A0.y, bp3);
            fma2(acc[2][0], A1.x, bp0); fma2(acc[2][1], A1.x, bp1);
            fma2(acc[2][2], A1.x, bp2); fma2(acc[2][3], A1.x, bp3);
            fma2(acc[3][0], A1.y, bp0); fma2(acc[3][1], A1.y, bp1);
            fma2(acc[3][2], A1.y, bp2); fma2(acc[3][3], A1.y, bp3);
        }
        __syncthreads();
    }

    float4 bias = *(const float4*)(g_bp + n0 + tx * 4);
    #pragma unroll
    for (int mp = 0; mp < 4; ++mp) {
        float lo0, hi0, lo1, hi1, lo2, hi2, lo3, hi3;
        unpack2(acc[mp][0], lo0, hi0);
        unpack2(acc[mp][1], lo1, hi1);
        unpack2(acc[mp][2], lo2, hi2);
        unpack2(acc[mp][3], lo3, hi3);
        int m = m0 + ty * 8 + mp * 2;
        float4 r0 = make_float4(lo0 + bias.x, lo1 + bias.y, lo2 + bias.z, lo3 + bias.w);
        float4 r1 = make_float4(hi0 + bias.x, hi1 + bias.y, hi2 + bias.z, hi3 + bias.w);
        *(float4*)&g_xp[(size_t)m * G4 + n0 + tx * 4]       = r0;
        *(float4*)&g_xp[(size_t)(m + 1) * G4 + n0 + tx * 4] = r1;
    }
}

// ---------------- phase 2: persistent LSTM recurrence (tensor cores) ----------
// 128 CTAs x 128 threads, 1 CTA/SM. CTA owns 32 permuted cols.
// z[64,32] = h[64,1024] @ Wh_slice via mma.sync m16n8k16 bf16, 3-term split
// (hi*Whi + hi*Wlo + lo*Whi) for fp32-level accuracy.
// Warp w handles batch rows 16w..16w+15 x all 32 cols (4 n-tiles of 8).
__global__ __launch_bounds__(NTHR, 1)
void lstm_mma(const float* __restrict__ init_c,
              const int*   __restrict__ lengths,
              float* __restrict__ out) {
    extern __shared__ __nv_bfloat16 sm[];
    __nv_bfloat16* wsH = sm;                               // [32][1032]
    __nv_bfloat16* wsL = sm + WS_HALVES;
    __nv_bfloat16* asH = sm + 2 * WS_HALVES;               // [64][136]
    __nv_bfloat16* asL = sm + 2 * WS_HALVES + AS_HALVES;

    const int tid  = threadIdx.x;
    const int wid  = tid >> 5;
    const int lane = tid & 31;
    const int n0   = blockIdx.x * 32;

    // ---- load W^T slice (rows n0..n0+31, all 1024 k) into smem, once ----
    #pragma unroll 4
    for (int i = 0; i < 32; ++i) {
        int idx = i * NTHR + tid;          // uint4 index, 0..4095
        int row = idx >> 7;                // 0..31
        int c16 = idx & 127;               // 16B unit within row
        *(uint4*)&wsH[row * WS_STRIDE + c16 * 8] =
            *(const uint4*)&g_WtHi[(size_t)(n0 + row) * 1024 + c16 * 8];
        *(uint4*)&wsL[row * WS_STRIDE + c16 * 8] =
            *(const uint4*)&g_WtLo[(size_t)(n0 + row) * 1024 + c16 * 8];
    }
    __syncthreads();

    // ---- which cells does this lane own? ----
    // per n-tile nt: even lane -> row r, odd lane -> row r+8 (r = lane>>2)
    const int b   = wid * 16 + (lane >> 2) + (lane & 1) * 8;
    const int hcb = (n0 >> 2) + ((lane & 3) >> 1);
    float creg[4];
    #pragma unroll
    for (int nt = 0; nt < 4; ++nt) creg[nt] = init_c[b * H_ + hcb + 2 * nt];
    const int len = lengths[b];

    // ---- ldmatrix base byte-offsets (shared address space) ----
    const u32 aOffH = su32(asH) + (u32)(((wid * 16 + (lane & 15)) * AS_STRIDE + (lane >> 4) * 8) * 2);
    const u32 aOffL = su32(asL) + (u32)(((wid * 16 + (lane & 15)) * AS_STRIDE + (lane >> 4) * 8) * 2);
    const u32 bRow0 = (lane & 7) + ((lane >> 4) & 1) * 8;
    const u32 bColB = (u32)(((lane >> 3) & 1) * 8) * 2;
    const u32 bOffH0 = su32(wsH) + bRow0 * (WS_STRIDE * 2) + bColB;
    const u32 bOffH1 = su32(wsH) + (bRow0 + 16) * (WS_STRIDE * 2) + bColB;
    const u32 bOffL0 = su32(wsL) + bRow0 * (WS_STRIDE * 2) + bColB;
    const u32 bOffL1 = su32(wsL) + (bRow0 + 16) * (WS_STRIDE * 2) + bColB;

    const size_t fc_off = (size_t)B_ * T_ * H_;
    const size_t fh_off = fc_off + (size_t)B_ * H_;
    volatile unsigned* vbar = &g_bar;

    for (int t = 0; t < T_; ++t) {
        // ---- prefetch xp quads (independent of h) ----
        float4 xpv[4];
        #pragma unroll
        for (int nt = 0; nt < 4; ++nt)
            xpv[nt] = __ldg((const float4*)&g_xp[((size_t)b * T_ + t) * G4 + (hcb + 2 * nt) * 4]);

        // ---- grid barrier: h writes of step t-1 visible ----
        __syncthreads();
        if (tid == 0) {
            __threadfence();
            atomicAdd(&g_bar, 1u);
            unsigned target = (unsigned)NCTA * (unsigned)(t + 1);
            while (*vbar < target) { }
            __threadfence();
        }
        __syncthreads();

        const __nv_bfloat16* hH = g_hbf[t & 1][0];
        const __nv_bfloat16* hL = g_hbf[t & 1][1];

        float dm[4][4], dc[4][4];
        #pragma unroll
        for (int nt = 0; nt < 4; ++nt)
            #pragma unroll
            for (int j = 0; j < 4; ++j) { dm[nt][j] = 0.f; dc[nt][j] = 0.f; }

        // ---- prefetch chunk 0 of h (both splits): [64 b][128 k] ----
        uint4 preH[8], preL[8];
        #pragma unroll
        for (int q = 0; q < 8; ++q) {
            int idx = q * NTHR + tid;      // 0..1023
            int row = idx >> 4;            // 0..63
            int c16 = idx & 15;
            preH[q] = *(const uint4*)&hH[row * H_ + c16 * 8];
            preL[q] = *(const uint4*)&hL[row * H_ + c16 * 8];
        }

        for (int ch = 0; ch < 8; ++ch) {
            // store staged chunk
            #pragma unroll
            for (int q = 0; q < 8; ++q) {
                int idx = q * NTHR + tid;
                int row = idx >> 4;
                int c16 = idx & 15;
                *(uint4*)&asH[row * AS_STRIDE + c16 * 8] = preH[q];
                *(uint4*)&asL[row * AS_STRIDE + c16 * 8] = preL[q];
            }
            __syncthreads();

            if (ch < 7) {
                #pragma unroll
                for (int q = 0; q < 8; ++q) {
                    int idx = q * NTHR + tid;
                    int row = idx >> 4;
                    int c16 = idx & 15;
                    preH[q] = *(const uint4*)&hH[row * H_ + (ch + 1) * 128 + c16 * 8];
                    preL[q] = *(const uint4*)&hL[row * H_ + (ch + 1) * 128 + c16 * 8];
                }
            }

            #pragma unroll
            for (int ks = 0; ks < 8; ++ks) {
                const u32 kByte = (u32)((ch * 128 + ks * 16) * 2);
                u32 ah[4], al[4];
                LDSM4(ah[0], ah[1], ah[2], ah[3], aOffH + (u32)(ks * 32));
                LDSM4(al[0], al[1], al[2], al[3], aOffL + (u32)(ks * 32));
                u32 bh0[4], bh1[4], bl0[4], bl1[4];
                LDSM4(bh0[0], bh0[1], bh0[2], bh0[3], bOffH0 + kByte);
                LDSM4(bh1[0], bh1[1], bh1[2], bh1[3], bOffH1 + kByte);
                LDSM4(bl0[0], bl0[1], bl0[2], bl0[3], bOffL0 + kByte);
                LDSM4(bl1[0], bl1[1], bl1[2], bl1[3], bOffL1 + kByte);

                // n-tiles: 0 -> (bh0[0],bh0[1]); 1 -> (bh0[2],bh0[3]);
                //          2 -> (bh1[0],bh1[1]); 3 -> (bh1[2],bh1[3])
                MMA_BF16(dm[0], ah, bh0[0], bh0[1]);
                MMA_BF16(dm[1], ah, bh0[2], bh0[3]);
                MMA_BF16(dm[2], ah, bh1[0], bh1[1]);
                MMA_BF16(dm[3], ah, bh1[2], bh1[3]);
                MMA_BF16(dc[0], ah, bl0[0], bl0[1]);
                MMA_BF16(dc[1], ah, bl0[2], bl0[3]);
                MMA_BF16(dc[2], ah, bl1[0], bl1[1]);
                MMA_BF16(dc[3], ah, bl1[2], bl1[3]);
                MMA_BF16(dc[0], al, bh0[0], bh0[1]);
                MMA_BF16(dc[1], al, bh0[2], bh0[3]);
                MMA_BF16(dc[2], al, bh1[0], bh1[1]);
                MMA_BF16(dc[3], al, bh1[2], bh1[3]);
            }
            __syncthreads();
        }

        // ---- epilogue: reassemble gate quads via shfl, cell update ----
        __nv_bfloat16* nxtH = g_hbf[(t + 1) & 1][0];
        __nv_bfloat16* nxtL = g_hbf[(t + 1) & 1][1];
        const bool odd = (lane & 1);
        #pragma unroll
        for (int nt = 0; nt < 4; ++nt) {
            float d0 = dm[nt][0] + dc[nt][0];
            float d1 = dm[nt][1] + dc[nt][1];
            float d2 = dm[nt][2] + dc[nt][2];
            float d3 = dm[nt][3] + dc[nt][3];
            float s0 = __shfl_xor_sync(0xffffffffu, d0, 1);
            float s1 = __shfl_xor_sync(0xffffffffu, d1, 1);
            float s2 = __shfl_xor_sync(0xffffffffu, d2, 1);
            float s3 = __shfl_xor_sync(0xffffffffu, d3, 1);
            float zi = odd ? s2 : d0;
            float zf = odd ? s3 : d1;
            float zg = odd ? d2 : s0;
            float zo = odd ? d3 : s1;
            zi += xpv[nt].x; zf += xpv[nt].y; zg += xpv[nt].z; zo += xpv[nt].w;
            float ig = sigmoidf_(zi);
            float fg = sigmoidf_(zf);
            float gg = tanhf(zg);
            float og = sigmoidf_(zo);
            float c = fg * creg[nt] + ig * gg;
            float h = og * tanhf(c);
            creg[nt] = c;
            int hc = hcb + 2 * nt;
            out[((size_t)b * T_ + t) * H_ + hc] = h;
            if (t == len - 1) {
                out[fc_off + b * H_ + hc] = c;
                out[fh_off + b * H_ + hc] = h;
            }
            __nv_bfloat16 hhi = __float2bfloat16(h);
            nxtH[b * H_ + hc] = hhi;
            nxtL[b * H_ + hc] = __float2bfloat16(h - __bfloat162float(hhi));
        }
    }
}

// ---------------- launch ----------------
extern "C" void kernel_launch(void* const* d_in, const int* in_sizes, int n_in,
                              void* d_out, int out_size) {
    const float* inputs  = (const float*)d_in[0];
    const int*   lengths = (const int*)  d_in[1];
    const float* init_c  = (const float*)d_in[2];
    const float* init_h  = (const float*)d_in[3];
    const float* Wi      = (const float*)d_in[4];
    const float* Wh      = (const float*)d_in[5];
    const float* b       = (const float*)d_in[6];
    float* out = (float*)d_out;

    cudaFuncSetAttribute(lstm_mma,
                         cudaFuncAttributeMaxDynamicSharedMemorySize, SMEM_BYTES);

    permute_kernel<<<(D_ * G4) / 256, 256>>>(Wi, b);
    wsplit_kernel<<<(G4 * H_) / 256, 256>>>(Wh);
    init_state<<<(B_ * H_) / 256, 256>>>(init_h);
    gemm_xproj<<<dim3(G4 / 64, (B_ * T_) / 128), 256>>>(inputs);
    lstm_mma<<<NCTA, NTHR, SMEM_BYTES>>>(init_c, lengths, out);
}

// round 12
// speedup vs baseline: 2.6687x; 1.3322x over previous
#include <cuda_runtime.h>
#include <cuda_bf16.h>
#include <math.h>

#define B_  64
#define T_  512
#define D_  1024
#define H_  1024
#define G4  4096   // 4*H

#define NCTA   128
#define NTHR   128

// recurrence smem layout (halves)
#define WS_STRIDE 1032
#define AS_STRIDE 136
#define WS_HALVES (32 * WS_STRIDE)
#define AS_HALVES (64 * AS_STRIDE)
#define SMEM_HALVES (2 * WS_HALVES + 2 * AS_HALVES)
#define SMEM_BYTES  (SMEM_HALVES * 2)       // 166912

// x_proj mma gemm tile: stride MUST be a multiple of 8 halves (16B) for
// uint4 STS / ldmatrix alignment. 40 halves = 80B; row word-offsets
// 20*i mod 32 are all distinct per 8-row group -> LDSM conflict-free.
#define XT_STR 40

// ---------------- device-global scratch ----------------
__device__ float g_bp[G4];                        // permuted bias
__device__ float g_xp[(size_t)B_ * T_ * G4];      // x_proj [b*T+t][4H] permuted cols
__device__ __nv_bfloat16 g_WtHi[(size_t)G4 * H_]; // Wh^T permuted [np][k], bf16 hi
__device__ __nv_bfloat16 g_WtLo[(size_t)G4 * H_];
__device__ __nv_bfloat16 g_WiTHi[(size_t)G4 * D_]; // Wi^T permuted [np][k], bf16 hi
__device__ __nv_bfloat16 g_WiTLo[(size_t)G4 * D_];
__device__ __nv_bfloat16 g_XHi[(size_t)B_ * T_ * D_]; // X split
__device__ __nv_bfloat16 g_XLo[(size_t)B_ * T_ * D_];
__device__ __nv_bfloat16 g_hbf[2][2][B_ * H_];    // [buf][hi/lo][b][k]
__device__ unsigned g_bar;

typedef unsigned long long ull;
typedef unsigned int u32;

__device__ __forceinline__ float sigmoidf_(float x) { return 1.0f / (1.0f + expf(-x)); }
__device__ __forceinline__ u32 su32(const void* p) {
    return (u32)__cvta_generic_to_shared(p);
}

#define LDSM4(r0, r1, r2, r3, addr) \
    asm volatile("ldmatrix.sync.aligned.m8n8.x4.shared.b16 {%0,%1,%2,%3}, [%4];" \
                 : "=r"(r0), "=r"(r1), "=r"(r2), "=r"(r3) : "r"(addr))

#define MMA_BF16(d, a, b0r, b1r) \
    asm volatile("mma.sync.aligned.m16n8k16.row.col.f32.bf16.bf16.f32 " \
                 "{%0,%1,%2,%3},{%4,%5,%6,%7},{%8,%9},{%0,%1,%2,%3};" \
                 : "+f"(d[0]), "+f"(d[1]), "+f"(d[2]), "+f"(d[3]) \
                 : "r"(a[0]), "r"(a[1]), "r"(a[2]), "r"(a[3]), "r"(b0r), "r"(b1r))

// ---------------- phase 0a: bias permute + barrier init ----------------
__global__ void prep_kernel(const float* __restrict__ b) {
    int idx = blockIdx.x * blockDim.x + threadIdx.x;   // 0 .. 4095
    g_bp[idx] = b[((idx & 3) << 10) + (idx >> 2)];
    if (idx == 0) g_bar = 0u;
}

// ---------------- phase 0b: Wh and Wi -> permuted transposed bf16 split ------
__global__ void wsplit_kernel(const float* __restrict__ Wh,
                              const float* __restrict__ Wi) {
    int idx = blockIdx.x * blockDim.x + threadIdx.x;   // 0 .. 4M-1
    int np = idx >> 10;
    int k  = idx & 1023;
    size_t src = (size_t)k * G4 + ((np & 3) << 10) + (np >> 2);
    float wh = Wh[src];
    __nv_bfloat16 hh = __float2bfloat16(wh);
    g_WtHi[idx] = hh;
    g_WtLo[idx] = __float2bfloat16(wh - __bfloat162float(hh));
    float wi = Wi[src];
    __nv_bfloat16 ih = __float2bfloat16(wi);
    g_WiTHi[idx] = ih;
    g_WiTLo[idx] = __float2bfloat16(wi - __bfloat162float(ih));
}

// ---------------- phase 0c: X -> bf16 split ----------------
__global__ void xsplit_kernel(const float* __restrict__ X) {
    int idx = blockIdx.x * blockDim.x + threadIdx.x;   // 0 .. 33.5M-1
    float v = X[idx];
    __nv_bfloat16 hi = __float2bfloat16(v);
    g_XHi[idx] = hi;
    g_XLo[idx] = __float2bfloat16(v - __bfloat162float(hi));
}

// ---------------- phase 0d: init h (bf16 split) ----------------
__global__ void init_state(const float* __restrict__ init_h) {
    int idx = blockIdx.x * blockDim.x + threadIdx.x;   // 0 .. 65535
    float v = init_h[idx];
    __nv_bfloat16 hi = __float2bfloat16(v);
    g_hbf[0][0][idx] = hi;
    g_hbf[0][1][idx] = __float2bfloat16(v - __bfloat162float(hi));
}

// ---------------- phase 1: x_proj via tensor cores (bf16 3-term split) -------
// C[32768,4096] = X @ Wi (+bias). BM=128 BN=64 BK=32, 256 thr, 8 warps (4m x 2n),
// warp tile 32m x 32n.
__global__ __launch_bounds__(256, 2)
void gemm_xproj_mma() {
    __shared__ __nv_bfloat16 xsH[128 * XT_STR];
    __shared__ __nv_bfloat16 xsL[128 * XT_STR];
    __shared__ __nv_bfloat16 wsH[64 * XT_STR];
    __shared__ __nv_bfloat16 wsL[64 * XT_STR];

    const int tid  = threadIdx.x;
    const int wid  = tid >> 5;
    const int lane = tid & 31;
    const int wm   = wid & 3;          // m group (32 rows)
    const int wn   = wid >> 2;         // n group (32 cols)
    const int m0   = blockIdx.y * 128;
    const int n0   = blockIdx.x * 64;

    // load mappings
    const int wrow = tid >> 2;              // 0..63
    const int wc16 = tid & 3;

    // LDSM byte offsets
    const u32 aRowB = (u32)((wm * 32 + (lane & 15)) * XT_STR * 2);
    const u32 aColB = (u32)((lane >> 4) * 16);
    const u32 aH0 = su32(xsH) + aRowB + aColB;
    const u32 aH1 = aH0 + (u32)(16 * XT_STR * 2);
    const u32 aL0 = su32(xsL) + aRowB + aColB;
    const u32 aL1 = aL0 + (u32)(16 * XT_STR * 2);
    const u32 bRow = (u32)(wn * 32 + (lane & 7) + ((lane >> 4) & 1) * 8);
    const u32 bColB = (u32)(((lane >> 3) & 1) * 16);
    const u32 bH0 = su32(wsH) + bRow * (XT_STR * 2) + bColB;          // n-tiles 0,1
    const u32 bH1 = bH0 + (u32)(16 * XT_STR * 2);                     // n-tiles 2,3
    const u32 bL0 = su32(wsL) + bRow * (XT_STR * 2) + bColB;
    const u32 bL1 = bL0 + (u32)(16 * XT_STR * 2);

    float acc[2][4][4];
    #pragma unroll
    for (int mt = 0; mt < 2; ++mt)
        #pragma unroll
        for (int nt = 0; nt < 4; ++nt)
            #pragma unroll
            for (int j = 0; j < 4; ++j) acc[mt][nt][j] = 0.f;

    // ---- preload chunk 0 ----
    uint4 sxH[2], sxL[2], swHr, swLr;
    {
        #pragma unroll
        for (int q = 0; q < 2; ++q) {
            int idx = q * 256 + tid;
            int row = idx >> 2, c16 = idx & 3;
            sxH[q] = *(const uint4*)&g_XHi[(size_t)(m0 + row) * 1024 + c16 * 8];
            sxL[q] = *(const uint4*)&g_XLo[(size_t)(m0 + row) * 1024 + c16 * 8];
        }
        swHr = *(const uint4*)&g_WiTHi[(size_t)(n0 + wrow) * 1024 + wc16 * 8];
        swLr = *(const uint4*)&g_WiTLo[(size_t)(n0 + wrow) * 1024 + wc16 * 8];
    }

    for (int kc = 0; kc < 32; ++kc) {
        // store staged chunk
        #pragma unroll
        for (int q = 0; q < 2; ++q) {
            int idx = q * 256 + tid;
            int row = idx >> 2, c16 = idx & 3;
            *(uint4*)&xsH[row * XT_STR + c16 * 8] = sxH[q];
            *(uint4*)&xsL[row * XT_STR + c16 * 8] = sxL[q];
        }
        *(uint4*)&wsH[wrow * XT_STR + wc16 * 8] = swHr;
        *(uint4*)&wsL[wrow * XT_STR + wc16 * 8] = swLr;
        __syncthreads();

        if (kc < 31) {
            int kb = (kc + 1) * 32;
            #pragma unroll
            for (int q = 0; q < 2; ++q) {
                int idx = q * 256 + tid;
                int row = idx >> 2, c16 = idx & 3;
                sxH[q] = *(const uint4*)&g_XHi[(size_t)(m0 + row) * 1024 + kb + c16 * 8];
                sxL[q] = *(const uint4*)&g_XLo[(size_t)(m0 + row) * 1024 + kb + c16 * 8];
            }
            swHr = *(const uint4*)&g_WiTHi[(size_t)(n0 + wrow) * 1024 + kb + wc16 * 8];
            swLr = *(const uint4*)&g_WiTLo[(size_t)(n0 + wrow) * 1024 + kb + wc16 * 8];
        }

        #pragma unroll
        for (int ks = 0; ks < 2; ++ks) {
            const u32 kb = (u32)(ks * 32);
            u32 aH[2][4], aL[2][4], bH[2][4], bL[2][4];
            LDSM4(aH[0][0], aH[0][1], aH[0][2], aH[0][3], aH0 + kb);
            LDSM4(aH[1][0], aH[1][1], aH[1][2], aH[1][3], aH1 + kb);
            LDSM4(aL[0][0], aL[0][1], aL[0][2], aL[0][3], aL0 + kb);
            LDSM4(aL[1][0], aL[1][1], aL[1][2], aL[1][3], aL1 + kb);
            LDSM4(bH[0][0], bH[0][1], bH[0][2], bH[0][3], bH0 + kb);
            LDSM4(bH[1][0], bH[1][1], bH[1][2], bH[1][3], bH1 + kb);
            LDSM4(bL[0][0], bL[0][1], bL[0][2], bL[0][3], bL0 + kb);
            LDSM4(bL[1][0], bL[1][1], bL[1][2], bL[1][3], bL1 + kb);

            #pragma unroll
            for (int mt = 0; mt < 2; ++mt) {
                #pragma unroll
                for (int ng = 0; ng < 2; ++ng) {
                    MMA_BF16(acc[mt][2 * ng + 0], aH[mt], bH[ng][0], bH[ng][1]);
                    MMA_BF16(acc[mt][2 * ng + 1], aH[mt], bH[ng][2], bH[ng][3]);
                    MMA_BF16(acc[mt][2 * ng + 0], aH[mt], bL[ng][0], bL[ng][1]);
                    MMA_BF16(acc[mt][2 * ng + 1], aH[mt], bL[ng][2], bL[ng][3]);
                    MMA_BF16(acc[mt][2 * ng + 0], aL[mt], bH[ng][0], bH[ng][1]);
                    MMA_BF16(acc[mt][2 * ng + 1], aL[mt], bH[ng][2], bH[ng][3]);
                }
            }
        }
        __syncthreads();
    }

    // ---- epilogue: add bias, store fp32 ----
    #pragma unroll
    for (int mt = 0; mt < 2; ++mt) {
        int r = m0 + wm * 32 + mt * 16 + (lane >> 2);
        #pragma unroll
        for (int nt = 0; nt < 4; ++nt) {
            int cc = n0 + wn * 32 + nt * 8 + 2 * (lane & 3);
            float2 b2 = *(const float2*)&g_bp[cc];
            float2 r0 = make_float2(acc[mt][nt][0] + b2.x, acc[mt][nt][1] + b2.y);
            float2 r1 = make_float2(acc[mt][nt][2] + b2.x, acc[mt][nt][3] + b2.y);
            *(float2*)&g_xp[(size_t)r * G4 + cc] = r0;
            *(float2*)&g_xp[(size_t)(r + 8) * G4 + cc] = r1;
        }
    }
}

// ---------------- phase 2: persistent LSTM recurrence (unchanged) ----------
__global__ __launch_bounds__(NTHR, 1)
void lstm_mma(const float* __restrict__ init_c,
              const int*   __restrict__ lengths,
              float* __restrict__ out) {
    extern __shared__ __nv_bfloat16 sm[];
    __nv_bfloat16* wsH = sm;
    __nv_bfloat16* wsL = sm + WS_HALVES;
    __nv_bfloat16* asH = sm + 2 * WS_HALVES;
    __nv_bfloat16* asL = sm + 2 * WS_HALVES + AS_HALVES;

    const int tid  = threadIdx.x;
    const int wid  = tid >> 5;
    const int lane = tid & 31;
    const int n0   = blockIdx.x * 32;

    #pragma unroll 4
    for (int i = 0; i < 32; ++i) {
        int idx = i * NTHR + tid;
        int row = idx >> 7;
        int c16 = idx & 127;
        *(uint4*)&wsH[row * WS_STRIDE + c16 * 8] =
            *(const uint4*)&g_WtHi[(size_t)(n0 + row) * 1024 + c16 * 8];
        *(uint4*)&wsL[row * WS_STRIDE + c16 * 8] =
            *(const uint4*)&g_WtLo[(size_t)(n0 + row) * 1024 + c16 * 8];
    }
    __syncthreads();

    const int b   = wid * 16 + (lane >> 2) + (lane & 1) * 8;
    const int hcb = (n0 >> 2) + ((lane & 3) >> 1);
    float creg[4];
    #pragma unroll
    for (int nt = 0; nt < 4; ++nt) creg[nt] = init_c[b * H_ + hcb + 2 * nt];
    const int len = lengths[b];

    const u32 aOffH = su32(asH) + (u32)(((wid * 16 + (lane & 15)) * AS_STRIDE + (lane >> 4) * 8) * 2);
    const u32 aOffL = su32(asL) + (u32)(((wid * 16 + (lane & 15)) * AS_STRIDE + (lane >> 4) * 8) * 2);
    const u32 bRow0 = (lane & 7) + ((lane >> 4) & 1) * 8;
    const u32 bColB = (u32)(((lane >> 3) & 1) * 8) * 2;
    const u32 bOffH0 = su32(wsH) + bRow0 * (WS_STRIDE * 2) + bColB;
    const u32 bOffH1 = su32(wsH) + (bRow0 + 16) * (WS_STRIDE * 2) + bColB;
    const u32 bOffL0 = su32(wsL) + bRow0 * (WS_STRIDE * 2) + bColB;
    const u32 bOffL1 = su32(wsL) + (bRow0 + 16) * (WS_STRIDE * 2) + bColB;

    const size_t fc_off = (size_t)B_ * T_ * H_;
    const size_t fh_off = fc_off + (size_t)B_ * H_;
    volatile unsigned* vbar = &g_bar;

    for (int t = 0; t < T_; ++t) {
        float4 xpv[4];
        #pragma unroll
        for (int nt = 0; nt < 4; ++nt)
            xpv[nt] = __ldg((const float4*)&g_xp[((size_t)b * T_ + t) * G4 + (hcb + 2 * nt) * 4]);

        __syncthreads();
        if (tid == 0) {
            __threadfence();
            atomicAdd(&g_bar, 1u);
            unsigned target = (unsigned)NCTA * (unsigned)(t + 1);
            while (*vbar < target) { }
            __threadfence();
        }
        __syncthreads();

        const __nv_bfloat16* hH = g_hbf[t & 1][0];
        const __nv_bfloat16* hL = g_hbf[t & 1][1];

        float dm[4][4], dc[4][4];
        #pragma unroll
        for (int nt = 0; nt < 4; ++nt)
            #pragma unroll
            for (int j = 0; j < 4; ++j) { dm[nt][j] = 0.f; dc[nt][j] = 0.f; }

        uint4 preH[8], preL[8];
        #pragma unroll
        for (int q = 0; q < 8; ++q) {
            int idx = q * NTHR + tid;
            int row = idx >> 4;
            int c16 = idx & 15;
            preH[q] = *(const uint4*)&hH[row * H_ + c16 * 8];
            preL[q] = *(const uint4*)&hL[row * H_ + c16 * 8];
        }

        for (int ch = 0; ch < 8; ++ch) {
            #pragma unroll
            for (int q = 0; q < 8; ++q) {
                int idx = q * NTHR + tid;
                int row = idx >> 4;
                int c16 = idx & 15;
                *(uint4*)&asH[row * AS_STRIDE + c16 * 8] = preH[q];
                *(uint4*)&asL[row * AS_STRIDE + c16 * 8] = preL[q];
            }
            __syncthreads();

            if (ch < 7) {
                #pragma unroll
                for (int q = 0; q < 8; ++q) {
                    int idx = q * NTHR + tid;
                    int row = idx >> 4;
                    int c16 = idx & 15;
                    preH[q] = *(const uint4*)&hH[row * H_ + (ch + 1) * 128 + c16 * 8];
                    preL[q] = *(const uint4*)&hL[row * H_ + (ch + 1) * 128 + c16 * 8];
                }
            }

            #pragma unroll
            for (int ks = 0; ks < 8; ++ks) {
                const u32 kByte = (u32)((ch * 128 + ks * 16) * 2);
                u32 ah[4], al[4];
                LDSM4(ah[0], ah[1], ah[2], ah[3], aOffH + (u32)(ks * 32));
                LDSM4(al[0], al[1], al[2], al[3], aOffL + (u32)(ks * 32));
                u32 bh0[4], bh1[4], bl0[4], bl1[4];
                LDSM4(bh0[0], bh0[1], bh0[2], bh0[3], bOffH0 + kByte);
                LDSM4(bh1[0], bh1[1], bh1[2], bh1[3], bOffH1 + kByte);
                LDSM4(bl0[0], bl0[1], bl0[2], bl0[3], bOffL0 + kByte);
                LDSM4(bl1[0], bl1[1], bl1[2], bl1[3], bOffL1 + kByte);

                MMA_BF16(dm[0], ah, bh0[0], bh0[1]);
                MMA_BF16(dm[1], ah, bh0[2], bh0[3]);
                MMA_BF16(dm[2], ah, bh1[0], bh1[1]);
                MMA_BF16(dm[3], ah, bh1[2], bh1[3]);
                MMA_BF16(dc[0], ah, bl0[0], bl0[1]);
                MMA_BF16(dc[1], ah, bl0[2], bl0[3]);
                MMA_BF16(dc[2], ah, bl1[0], bl1[1]);
                MMA_BF16(dc[3], ah, bl1[2], bl1[3]);
                MMA_BF16(dc[0], al, bh0[0], bh0[1]);
                MMA_BF16(dc[1], al, bh0[2], bh0[3]);
                MMA_BF16(dc[2], al, bh1[0], bh1[1]);
                MMA_BF16(dc[3], al, bh1[2], bh1[3]);
            }
            __syncthreads();
        }

        __nv_bfloat16* nxtH = g_hbf[(t + 1) & 1][0];
        __nv_bfloat16* nxtL = g_hbf[(t + 1) & 1][1];
        const bool odd = (lane & 1);
        #pragma unroll
        for (int nt = 0; nt < 4; ++nt) {
            float d0 = dm[nt][0] + dc[nt][0];
            float d1 = dm[nt][1] + dc[nt][1];
            float d2 = dm[nt][2] + dc[nt][2];
            float d3 = dm[nt][3] + dc[nt][3];
            float s0 = __shfl_xor_sync(0xffffffffu, d0, 1);
            float s1 = __shfl_xor_sync(0xffffffffu, d1, 1);
            float s2 = __shfl_xor_sync(0xffffffffu, d2, 1);
            float s3 = __shfl_xor_sync(0xffffffffu, d3, 1);
            float zi = odd ? s2 : d0;
            float zf = odd ? s3 : d1;
            float zg = odd ? d2 : s0;
            float zo = odd ? d3 : s1;
            zi += xpv[nt].x; zf += xpv[nt].y; zg += xpv[nt].z; zo += xpv[nt].w;
            float ig = sigmoidf_(zi);
            float fg = sigmoidf_(zf);
            float gg = tanhf(zg);
            float og = sigmoidf_(zo);
            float c = fg * creg[nt] + ig * gg;
            float h = og * tanhf(c);
            creg[nt] = c;
            int hc = hcb + 2 * nt;
            out[((size_t)b * T_ + t) * H_ + hc] = h;
            if (t == len - 1) {
                out[fc_off + b * H_ + hc] = c;
                out[fh_off + b * H_ + hc] = h;
            }
            __nv_bfloat16 hhi = __float2bfloat16(h);
            nxtH[b * H_ + hc] = hhi;
            nxtL[b * H_ + hc] = __float2bfloat16(h - __bfloat162float(hhi));
        }
    }
}

// ---------------- launch ----------------
extern "C" void kernel_launch(void* const* d_in, const int* in_sizes, int n_in,
                              void* d_out, int out_size) {
    const float* inputs  = (const float*)d_in[0];
    const int*   lengths = (const int*)  d_in[1];
    const float* init_c  = (const float*)d_in[2];
    const float* init_h  = (const float*)d_in[3];
    const float* Wi      = (const float*)d_in[4];
    const float* Wh      = (const float*)d_in[5];
    const float* b       = (const float*)d_in[6];
    float* out = (float*)d_out;

    cudaFuncSetAttribute(lstm_mma,
                         cudaFuncAttributeMaxDynamicSharedMemorySize, SMEM_BYTES);

    prep_kernel<<<G4 / 256, 256>>>(b);
    wsplit_kernel<<<(G4 * H_) / 256, 256>>>(Wh, Wi);
    xsplit_kernel<<<(B_ * T_ * D_) / 256, 256>>>(inputs);
    init_state<<<(B_ * H_) / 256, 256>>>(init_h);
    gemm_xproj_mma<<<dim3(G4 / 64, (B_ * T_) / 128), 256>>>();
    lstm_mma<<<NCTA, NTHR, SMEM_BYTES>>>(init_c, lengths, out);
}